// round 2
// baseline (speedup 1.0000x reference)
#include <cuda_runtime.h>

#define N_NODES 100000
#define N_EDGES 3200000
#define D 128

// Scratch (device globals; no allocation allowed)
__device__ float g_h[(size_t)N_NODES * D];   // 51.2 MB: h = x @ W^T
__device__ float g_Wt[D * D];                // W transposed to k-major

// ---------------------------------------------------------------------------
// W transpose: g_Wt[k][o] = W[o][k]
// ---------------------------------------------------------------------------
__global__ void transpose_w_kernel(const float* __restrict__ W) {
    int idx = blockIdx.x * blockDim.x + threadIdx.x;
    if (idx < D * D) {
        int o = idx / D;
        int k = idx % D;
        g_Wt[k * D + o] = W[o * D + k];
    }
}

// ---------------------------------------------------------------------------
// GEMM: h[n][o] = sum_k x[n][k] * W[o][k]   (reads g_Wt k-major)
// BM=64 nodes per block, BN=128 (full D_OUT), BK=16, 256 threads.
// Thread microtile: 8 nodes x 4 outputs.
// ---------------------------------------------------------------------------
#define BM 64
#define BK 16

__global__ __launch_bounds__(256) void gemm_kernel(const float* __restrict__ x) {
    __shared__ float xs[BM][BK];
    __shared__ float ws[BK][D];

    int tid  = threadIdx.x;
    int lane = tid & 31;      // output group: o = lane*4 .. +3
    int rgrp = tid >> 5;      // node group:   n = n_base + rgrp*8 + i
    int n_base = blockIdx.x * BM;

    float acc[8][4];
#pragma unroll
    for (int i = 0; i < 8; i++)
#pragma unroll
        for (int j = 0; j < 4; j++) acc[i][j] = 0.0f;

    for (int kb = 0; kb < D; kb += BK) {
        // Load x tile: 64 nodes x 16 k  (float4 per thread)
        {
            int node = tid >> 2;           // 0..63
            int k4   = (tid & 3) * 4;      // 0,4,8,12
            int n    = n_base + node;
            float4 v = make_float4(0.f, 0.f, 0.f, 0.f);
            if (n < N_NODES) v = *(const float4*)&x[(size_t)n * D + kb + k4];
            *(float4*)&xs[node][k4] = v;
        }
        // Load W tile (already k-major): 16 k x 128 o  (2x float4 per thread)
        {
            int k  = tid >> 4;             // 0..15
            int o8 = (tid & 15) * 8;       // 0..120 step 8
            float4 a = *(const float4*)&g_Wt[(kb + k) * D + o8];
            float4 b = *(const float4*)&g_Wt[(kb + k) * D + o8 + 4];
            *(float4*)&ws[k][o8]     = a;
            *(float4*)&ws[k][o8 + 4] = b;
        }
        __syncthreads();

#pragma unroll
        for (int k = 0; k < BK; k++) {
            float4 w4 = *(const float4*)&ws[k][lane * 4];
#pragma unroll
            for (int i = 0; i < 8; i++) {
                float xv = xs[rgrp * 8 + i][k];
                acc[i][0] += xv * w4.x;
                acc[i][1] += xv * w4.y;
                acc[i][2] += xv * w4.z;
                acc[i][3] += xv * w4.w;
            }
        }
        __syncthreads();
    }

#pragma unroll
    for (int i = 0; i < 8; i++) {
        int n = n_base + rgrp * 8 + i;
        if (n < N_NODES) {
            float4 v = make_float4(acc[i][0], acc[i][1], acc[i][2], acc[i][3]);
            *(float4*)&g_h[(size_t)n * D + lane * 4] = v;
        }
    }
}

// ---------------------------------------------------------------------------
// Zero the output accumulator (d_out is poisoned before each timed replay)
// ---------------------------------------------------------------------------
__global__ void zero_kernel(float4* __restrict__ out) {
    size_t i = (size_t)blockIdx.x * blockDim.x + threadIdx.x;
    out[i] = make_float4(0.f, 0.f, 0.f, 0.f);
}

// ---------------------------------------------------------------------------
// Scatter: out[rows[e]] += vals[e] * h[cols[e]]
// One warp per edge; each lane handles 4 contiguous features (float4 gather,
// 4 scalar atomicAdds -> warp-coalesced into contiguous 512B = 16 sectors).
// Indices are int32 (JAX x64 disabled downcasts the reference's int64).
// ---------------------------------------------------------------------------
__global__ __launch_bounds__(256) void scatter_kernel(
    const int* __restrict__ rows,
    const int* __restrict__ cols,
    const float* __restrict__ vals,
    float* __restrict__ out)
{
    int e    = blockIdx.x * 8 + (threadIdx.x >> 5);   // 8 warps per block
    int lane = threadIdx.x & 31;

    int   r = rows[e];   // broadcast load (same addr across warp)
    int   c = cols[e];
    float v = vals[e];

    float4 hv = *(const float4*)&g_h[(size_t)c * D + lane * 4];
    float* op = &out[(size_t)r * D + lane * 4];
    atomicAdd(op + 0, v * hv.x);
    atomicAdd(op + 1, v * hv.y);
    atomicAdd(op + 2, v * hv.z);
    atomicAdd(op + 3, v * hv.w);
}

// ---------------------------------------------------------------------------
// In-place ReLU on the output
// ---------------------------------------------------------------------------
__global__ void relu_kernel(float4* __restrict__ out) {
    size_t i = (size_t)blockIdx.x * blockDim.x + threadIdx.x;
    float4 v = out[i];
    v.x = fmaxf(v.x, 0.f);
    v.y = fmaxf(v.y, 0.f);
    v.z = fmaxf(v.z, 0.f);
    v.w = fmaxf(v.w, 0.f);
    out[i] = v;
}

// ---------------------------------------------------------------------------
// kernel_launch: transpose W -> GEMM -> zero -> scatter -> relu
// Inputs (metadata order): x f32[100000,128], adj_rows i32[3.2M],
// adj_cols i32[3.2M], adj_vals f32[3.2M], W f32[128,128]. Output f32[100000,128].
// ---------------------------------------------------------------------------
extern "C" void kernel_launch(void* const* d_in, const int* in_sizes, int n_in,
                              void* d_out, int out_size) {
    const float* x    = (const float*)d_in[0];
    const int*   rows = (const int*)d_in[1];
    const int*   cols = (const int*)d_in[2];
    const float* vals = (const float*)d_in[3];
    const float* W    = (const float*)d_in[4];
    float*       out  = (float*)d_out;

    // 1. Transpose W (16384 elems)
    transpose_w_kernel<<<(D * D + 255) / 256, 256>>>(W);

    // 2. GEMM h = x @ W^T
    gemm_kernel<<<(N_NODES + BM - 1) / BM, 256>>>(x);

    // 3. Zero output accumulator: 100000*128/4 = 3.2M float4 -> 12500 blocks
    zero_kernel<<<(N_NODES * D / 4) / 256, 256>>>((float4*)out);

    // 4. Scatter-aggregate: 3.2M edges, 8 edges/block -> 400000 blocks
    scatter_kernel<<<N_EDGES / 8, 256>>>(rows, cols, vals, out);

    // 5. ReLU in place
    relu_kernel<<<(N_NODES * D / 4) / 256, 256>>>((float4*)out);
}

// round 3
// speedup vs baseline: 3.6875x; 3.6875x over previous
#include <cuda_runtime.h>

#define N_NODES 100000
#define N_EDGES 3200000
#define D 128

#define SCAN_BLK 1024
#define NSCAN_BLKS ((N_NODES + SCAN_BLK - 1) / SCAN_BLK)   // 98

// ---------------- scratch (device globals; no allocation allowed) ----------
__device__ float g_h[(size_t)N_NODES * D];     // 51.2 MB: h = x @ W^T
__device__ float g_Wt[D * D];                  // W transposed (k-major)
__device__ int   g_deg[N_NODES];               // per-row degree
__device__ int   g_off[N_NODES];               // exclusive prefix (row start)
__device__ int   g_cur[N_NODES];               // fill cursor
__device__ int   g_bsum[NSCAN_BLKS];           // scan block sums
__device__ int2  g_epair[N_EDGES];             // {col, val-as-bits} grouped by row

// ---------------------------------------------------------------------------
// W transpose: g_Wt[k][o] = W[o][k]
// ---------------------------------------------------------------------------
__global__ void transpose_w_kernel(const float* __restrict__ W) {
    int idx = blockIdx.x * blockDim.x + threadIdx.x;
    if (idx < D * D) {
        int o = idx / D;
        int k = idx % D;
        g_Wt[k * D + o] = W[o * D + k];
    }
}

// ---------------------------------------------------------------------------
// GEMM: h[n][o] = sum_k x[n][k] * W[o][k]
// ---------------------------------------------------------------------------
#define BM 64
#define BK 16

__global__ __launch_bounds__(256) void gemm_kernel(const float* __restrict__ x) {
    __shared__ float xs[BM][BK];
    __shared__ float ws[BK][D];

    int tid  = threadIdx.x;
    int lane = tid & 31;
    int rgrp = tid >> 5;
    int n_base = blockIdx.x * BM;

    float acc[8][4];
#pragma unroll
    for (int i = 0; i < 8; i++)
#pragma unroll
        for (int j = 0; j < 4; j++) acc[i][j] = 0.0f;

    for (int kb = 0; kb < D; kb += BK) {
        {
            int node = tid >> 2;
            int k4   = (tid & 3) * 4;
            int n    = n_base + node;
            float4 v = make_float4(0.f, 0.f, 0.f, 0.f);
            if (n < N_NODES) v = *(const float4*)&x[(size_t)n * D + kb + k4];
            *(float4*)&xs[node][k4] = v;
        }
        {
            int k  = tid >> 4;
            int o8 = (tid & 15) * 8;
            float4 a = *(const float4*)&g_Wt[(kb + k) * D + o8];
            float4 b = *(const float4*)&g_Wt[(kb + k) * D + o8 + 4];
            *(float4*)&ws[k][o8]     = a;
            *(float4*)&ws[k][o8 + 4] = b;
        }
        __syncthreads();

#pragma unroll
        for (int k = 0; k < BK; k++) {
            float4 w4 = *(const float4*)&ws[k][lane * 4];
#pragma unroll
            for (int i = 0; i < 8; i++) {
                float xv = xs[rgrp * 8 + i][k];
                acc[i][0] += xv * w4.x;
                acc[i][1] += xv * w4.y;
                acc[i][2] += xv * w4.z;
                acc[i][3] += xv * w4.w;
            }
        }
        __syncthreads();
    }

#pragma unroll
    for (int i = 0; i < 8; i++) {
        int n = n_base + rgrp * 8 + i;
        if (n < N_NODES) {
            float4 v = make_float4(acc[i][0], acc[i][1], acc[i][2], acc[i][3]);
            *(float4*)&g_h[(size_t)n * D + lane * 4] = v;
        }
    }
}

// ---------------------------------------------------------------------------
// CSR build
// ---------------------------------------------------------------------------
__global__ void zero_deg_kernel() {
    int i = blockIdx.x * blockDim.x + threadIdx.x;
    if (i < N_NODES) g_deg[i] = 0;
}

__global__ void count_kernel(const int* __restrict__ rows) {
    int e = blockIdx.x * blockDim.x + threadIdx.x;
    if (e < N_EDGES) atomicAdd(&g_deg[rows[e]], 1);
}

// Block-level inclusive scan -> per-element exclusive offsets + block sums
__global__ __launch_bounds__(SCAN_BLK) void scan1_kernel() {
    __shared__ int s[SCAN_BLK];
    int i = blockIdx.x * SCAN_BLK + threadIdx.x;
    int v = (i < N_NODES) ? g_deg[i] : 0;
    s[threadIdx.x] = v;
    __syncthreads();
#pragma unroll
    for (int d = 1; d < SCAN_BLK; d <<= 1) {
        int t = 0;
        if (threadIdx.x >= d) t = s[threadIdx.x - d];
        __syncthreads();
        if (threadIdx.x >= d) s[threadIdx.x] += t;
        __syncthreads();
    }
    if (i < N_NODES) g_off[i] = s[threadIdx.x] - v;   // exclusive within block
    if (threadIdx.x == SCAN_BLK - 1) g_bsum[blockIdx.x] = s[SCAN_BLK - 1];
}

// Serial scan of the 98 block sums (trivial)
__global__ void scan2_kernel() {
    if (threadIdx.x == 0) {
        int acc = 0;
        for (int b = 0; b < NSCAN_BLKS; b++) {
            int t = g_bsum[b];
            g_bsum[b] = acc;
            acc += t;
        }
    }
}

__global__ void scan3_kernel() {
    int i = blockIdx.x * blockDim.x + threadIdx.x;
    if (i < N_NODES) {
        int o = g_off[i] + g_bsum[i / SCAN_BLK];
        g_off[i] = o;
        g_cur[i] = o;
    }
}

__global__ void fill_kernel(const int* __restrict__ rows,
                            const int* __restrict__ cols,
                            const float* __restrict__ vals) {
    int e = blockIdx.x * blockDim.x + threadIdx.x;
    if (e < N_EDGES) {
        int r = rows[e];
        int p = atomicAdd(&g_cur[r], 1);
        g_epair[p] = make_int2(cols[e], __float_as_int(vals[e]));
    }
}

// ---------------------------------------------------------------------------
// Aggregate + ReLU: one warp per node, register accumulation, no atomics.
// lane handles 4 contiguous features (float4) -> 512B/warp/edge coalesced.
// ---------------------------------------------------------------------------
__global__ __launch_bounds__(256) void aggregate_kernel(float* __restrict__ out) {
    int n = blockIdx.x * 8 + (threadIdx.x >> 5);
    if (n >= N_NODES) return;
    int lane = threadIdx.x & 31;

    int s = g_off[n];
    int d = g_deg[n];
    int fofs = lane * 4;

    float4 acc = make_float4(0.f, 0.f, 0.f, 0.f);

    int j = 0;
    // 4-way unrolled body for MLP against ~250cyc L2 gather latency
    for (; j + 4 <= d; j += 4) {
        int2 p0 = g_epair[s + j + 0];
        int2 p1 = g_epair[s + j + 1];
        int2 p2 = g_epair[s + j + 2];
        int2 p3 = g_epair[s + j + 3];
        float4 h0 = *(const float4*)&g_h[(size_t)p0.x * D + fofs];
        float4 h1 = *(const float4*)&g_h[(size_t)p1.x * D + fofs];
        float4 h2 = *(const float4*)&g_h[(size_t)p2.x * D + fofs];
        float4 h3 = *(const float4*)&g_h[(size_t)p3.x * D + fofs];
        float v0 = __int_as_float(p0.y), v1 = __int_as_float(p1.y);
        float v2 = __int_as_float(p2.y), v3 = __int_as_float(p3.y);
        acc.x += v0 * h0.x; acc.y += v0 * h0.y; acc.z += v0 * h0.z; acc.w += v0 * h0.w;
        acc.x += v1 * h1.x; acc.y += v1 * h1.y; acc.z += v1 * h1.z; acc.w += v1 * h1.w;
        acc.x += v2 * h2.x; acc.y += v2 * h2.y; acc.z += v2 * h2.z; acc.w += v2 * h2.w;
        acc.x += v3 * h3.x; acc.y += v3 * h3.y; acc.z += v3 * h3.z; acc.w += v3 * h3.w;
    }
    for (; j < d; j++) {
        int2 p = g_epair[s + j];
        float4 hv = *(const float4*)&g_h[(size_t)p.x * D + fofs];
        float v = __int_as_float(p.y);
        acc.x += v * hv.x; acc.y += v * hv.y; acc.z += v * hv.z; acc.w += v * hv.w;
    }

    acc.x = fmaxf(acc.x, 0.f);
    acc.y = fmaxf(acc.y, 0.f);
    acc.z = fmaxf(acc.z, 0.f);
    acc.w = fmaxf(acc.w, 0.f);
    *(float4*)&out[(size_t)n * D + fofs] = acc;
}

// ---------------------------------------------------------------------------
// kernel_launch
// ---------------------------------------------------------------------------
extern "C" void kernel_launch(void* const* d_in, const int* in_sizes, int n_in,
                              void* d_out, int out_size) {
    const float* x    = (const float*)d_in[0];
    const int*   rows = (const int*)d_in[1];
    const int*   cols = (const int*)d_in[2];
    const float* vals = (const float*)d_in[3];
    const float* W    = (const float*)d_in[4];
    float*       out  = (float*)d_out;

    const int EB = (N_EDGES + 255) / 256;   // 12500
    const int NB = (N_NODES + 255) / 256;   // 391

    // Dense path
    transpose_w_kernel<<<(D * D + 255) / 256, 256>>>(W);
    gemm_kernel<<<(N_NODES + BM - 1) / BM, 256>>>(x);

    // CSR build (overlaps GEMM on the same stream? No — serialized, but cheap)
    zero_deg_kernel<<<NB, 256>>>();
    count_kernel<<<EB, 256>>>(rows);
    scan1_kernel<<<NSCAN_BLKS, SCAN_BLK>>>();
    scan2_kernel<<<1, 32>>>();
    scan3_kernel<<<NB, 256>>>();
    fill_kernel<<<EB, 256>>>(rows, cols, vals);

    // Gather-accumulate + fused ReLU (writes every output row)
    aggregate_kernel<<<(N_NODES + 7) / 8, 256>>>(out);
}

// round 4
// speedup vs baseline: 4.1930x; 1.1371x over previous
#include <cuda_runtime.h>
#include <cuda_fp16.h>

#define N_NODES 100000
#define N_EDGES 3200000
#define D 128

#define SCAN_BLK 1024
#define NSCAN_BLKS ((N_NODES + SCAN_BLK - 1) / SCAN_BLK)   // 98

// ---------------- scratch (device globals; no allocation allowed) ----------
__device__ __half g_h[(size_t)N_NODES * D];    // 25.6 MB: h = x @ W^T (fp16)
__device__ float  g_Wt[D * D];                 // W transposed (k-major)
__device__ int    g_deg[N_NODES];              // per-row degree
__device__ int    g_off[N_NODES];              // exclusive prefix (row start)
__device__ int    g_cur[N_NODES];              // fill cursor
__device__ int    g_bsum[NSCAN_BLKS];          // scan block sums
__device__ int2   g_epair[N_EDGES];            // {col, val-as-bits} grouped by row

// ---------------------------------------------------------------------------
// W transpose: g_Wt[k][o] = W[o][k]
// ---------------------------------------------------------------------------
__global__ void transpose_w_kernel(const float* __restrict__ W) {
    int idx = blockIdx.x * blockDim.x + threadIdx.x;
    if (idx < D * D) {
        int o = idx / D;
        int k = idx % D;
        g_Wt[k * D + o] = W[o * D + k];
    }
}

// ---------------------------------------------------------------------------
// GEMM: h[n][o] = sum_k x[n][k] * W[o][k], fp32 compute, fp16 store
// ---------------------------------------------------------------------------
#define BM 64
#define BK 16

__global__ __launch_bounds__(256) void gemm_kernel(const float* __restrict__ x) {
    __shared__ float xs[BM][BK];
    __shared__ float ws[BK][D];

    int tid  = threadIdx.x;
    int lane = tid & 31;
    int rgrp = tid >> 5;
    int n_base = blockIdx.x * BM;

    float acc[8][4];
#pragma unroll
    for (int i = 0; i < 8; i++)
#pragma unroll
        for (int j = 0; j < 4; j++) acc[i][j] = 0.0f;

    for (int kb = 0; kb < D; kb += BK) {
        {
            int node = tid >> 2;
            int k4   = (tid & 3) * 4;
            int n    = n_base + node;
            float4 v = make_float4(0.f, 0.f, 0.f, 0.f);
            if (n < N_NODES) v = *(const float4*)&x[(size_t)n * D + kb + k4];
            *(float4*)&xs[node][k4] = v;
        }
        {
            int k  = tid >> 4;
            int o8 = (tid & 15) * 8;
            float4 a = *(const float4*)&g_Wt[(kb + k) * D + o8];
            float4 b = *(const float4*)&g_Wt[(kb + k) * D + o8 + 4];
            *(float4*)&ws[k][o8]     = a;
            *(float4*)&ws[k][o8 + 4] = b;
        }
        __syncthreads();

#pragma unroll
        for (int k = 0; k < BK; k++) {
            float4 w4 = *(const float4*)&ws[k][lane * 4];
#pragma unroll
            for (int i = 0; i < 8; i++) {
                float xv = xs[rgrp * 8 + i][k];
                acc[i][0] += xv * w4.x;
                acc[i][1] += xv * w4.y;
                acc[i][2] += xv * w4.z;
                acc[i][3] += xv * w4.w;
            }
        }
        __syncthreads();
    }

#pragma unroll
    for (int i = 0; i < 8; i++) {
        int n = n_base + rgrp * 8 + i;
        if (n < N_NODES) {
            half2 lo = __floats2half2_rn(acc[i][0], acc[i][1]);
            half2 hi = __floats2half2_rn(acc[i][2], acc[i][3]);
            uint2 packed;
            packed.x = *(unsigned*)&lo;
            packed.y = *(unsigned*)&hi;
            *(uint2*)&g_h[(size_t)n * D + lane * 4] = packed;
        }
    }
}

// ---------------------------------------------------------------------------
// CSR build
// ---------------------------------------------------------------------------
__global__ void zero_deg_kernel() {
    int i = blockIdx.x * blockDim.x + threadIdx.x;
    if (i < N_NODES) g_deg[i] = 0;
}

// 4 edges per thread (int4 loads)
__global__ void count_kernel(const int4* __restrict__ rows4) {
    int t = blockIdx.x * blockDim.x + threadIdx.x;
    if (t < N_EDGES / 4) {
        int4 r = rows4[t];
        atomicAdd(&g_deg[r.x], 1);
        atomicAdd(&g_deg[r.y], 1);
        atomicAdd(&g_deg[r.z], 1);
        atomicAdd(&g_deg[r.w], 1);
    }
}

__global__ __launch_bounds__(SCAN_BLK) void scan1_kernel() {
    __shared__ int s[SCAN_BLK];
    int i = blockIdx.x * SCAN_BLK + threadIdx.x;
    int v = (i < N_NODES) ? g_deg[i] : 0;
    s[threadIdx.x] = v;
    __syncthreads();
#pragma unroll
    for (int d = 1; d < SCAN_BLK; d <<= 1) {
        int t = 0;
        if (threadIdx.x >= d) t = s[threadIdx.x - d];
        __syncthreads();
        if (threadIdx.x >= d) s[threadIdx.x] += t;
        __syncthreads();
    }
    if (i < N_NODES) g_off[i] = s[threadIdx.x] - v;
    if (threadIdx.x == SCAN_BLK - 1) g_bsum[blockIdx.x] = s[SCAN_BLK - 1];
}

__global__ void scan2_kernel() {
    if (threadIdx.x == 0) {
        int acc = 0;
        for (int b = 0; b < NSCAN_BLKS; b++) {
            int t = g_bsum[b];
            g_bsum[b] = acc;
            acc += t;
        }
    }
}

__global__ void scan3_kernel() {
    int i = blockIdx.x * blockDim.x + threadIdx.x;
    if (i < N_NODES) {
        int o = g_off[i] + g_bsum[i / SCAN_BLK];
        g_off[i] = o;
        g_cur[i] = o;
    }
}

// 4 edges per thread (int4/float4 loads)
__global__ void fill_kernel(const int4* __restrict__ rows4,
                            const int4* __restrict__ cols4,
                            const float4* __restrict__ vals4) {
    int t = blockIdx.x * blockDim.x + threadIdx.x;
    if (t < N_EDGES / 4) {
        int4   r = rows4[t];
        int4   c = cols4[t];
        float4 v = vals4[t];
        int p0 = atomicAdd(&g_cur[r.x], 1);
        g_epair[p0] = make_int2(c.x, __float_as_int(v.x));
        int p1 = atomicAdd(&g_cur[r.y], 1);
        g_epair[p1] = make_int2(c.y, __float_as_int(v.y));
        int p2 = atomicAdd(&g_cur[r.z], 1);
        g_epair[p2] = make_int2(c.z, __float_as_int(v.z));
        int p3 = atomicAdd(&g_cur[r.w], 1);
        g_epair[p3] = make_int2(c.w, __float_as_int(v.w));
    }
}

// ---------------------------------------------------------------------------
// Aggregate + ReLU: one warp per node; lane handles 4 features (8B fp16 load)
// ---------------------------------------------------------------------------
__device__ __forceinline__ void fma_h4(float4& acc, float v, uint2 raw) {
    float2 lo = __half22float2(*(half2*)&raw.x);
    float2 hi = __half22float2(*(half2*)&raw.y);
    acc.x += v * lo.x;
    acc.y += v * lo.y;
    acc.z += v * hi.x;
    acc.w += v * hi.y;
}

__global__ __launch_bounds__(256) void aggregate_kernel(float* __restrict__ out) {
    int n = blockIdx.x * 8 + (threadIdx.x >> 5);
    if (n >= N_NODES) return;
    int lane = threadIdx.x & 31;

    int s = g_off[n];
    int d = g_deg[n];
    int fofs = lane * 4;

    float4 acc = make_float4(0.f, 0.f, 0.f, 0.f);

    int j = 0;
    for (; j + 4 <= d; j += 4) {
        int2 p0 = g_epair[s + j + 0];
        int2 p1 = g_epair[s + j + 1];
        int2 p2 = g_epair[s + j + 2];
        int2 p3 = g_epair[s + j + 3];
        uint2 h0 = *(const uint2*)&g_h[(size_t)p0.x * D + fofs];
        uint2 h1 = *(const uint2*)&g_h[(size_t)p1.x * D + fofs];
        uint2 h2 = *(const uint2*)&g_h[(size_t)p2.x * D + fofs];
        uint2 h3 = *(const uint2*)&g_h[(size_t)p3.x * D + fofs];
        fma_h4(acc, __int_as_float(p0.y), h0);
        fma_h4(acc, __int_as_float(p1.y), h1);
        fma_h4(acc, __int_as_float(p2.y), h2);
        fma_h4(acc, __int_as_float(p3.y), h3);
    }
    for (; j < d; j++) {
        int2 p = g_epair[s + j];
        uint2 hv = *(const uint2*)&g_h[(size_t)p.x * D + fofs];
        fma_h4(acc, __int_as_float(p.y), hv);
    }

    acc.x = fmaxf(acc.x, 0.f);
    acc.y = fmaxf(acc.y, 0.f);
    acc.z = fmaxf(acc.z, 0.f);
    acc.w = fmaxf(acc.w, 0.f);
    *(float4*)&out[(size_t)n * D + fofs] = acc;
}

// ---------------------------------------------------------------------------
// kernel_launch
// ---------------------------------------------------------------------------
extern "C" void kernel_launch(void* const* d_in, const int* in_sizes, int n_in,
                              void* d_out, int out_size) {
    const float* x    = (const float*)d_in[0];
    const int*   rows = (const int*)d_in[1];
    const int*   cols = (const int*)d_in[2];
    const float* vals = (const float*)d_in[3];
    const float* W    = (const float*)d_in[4];
    float*       out  = (float*)d_out;

    const int EB4 = (N_EDGES / 4 + 255) / 256;  // 3125
    const int NB  = (N_NODES + 255) / 256;      // 391

    // Dense path
    transpose_w_kernel<<<(D * D + 255) / 256, 256>>>(W);
    gemm_kernel<<<(N_NODES + BM - 1) / BM, 256>>>(x);

    // CSR build
    zero_deg_kernel<<<NB, 256>>>();
    count_kernel<<<EB4, 256>>>((const int4*)rows);
    scan1_kernel<<<NSCAN_BLKS, SCAN_BLK>>>();
    scan2_kernel<<<1, 32>>>();
    scan3_kernel<<<NB, 256>>>();
    fill_kernel<<<EB4, 256>>>((const int4*)rows, (const int4*)cols,
                              (const float4*)vals);

    // Gather-accumulate + fused ReLU
    aggregate_kernel<<<(N_NODES + 7) / 8, 256>>>(out);
}

// round 5
// speedup vs baseline: 5.0214x; 1.1976x over previous
#include <cuda_runtime.h>
#include <cuda_fp16.h>

#define N_NODES 100000
#define N_EDGES 3200000
#define D 128

#define SCAN_BLK 1024
#define NSCAN_BLKS ((N_NODES + SCAN_BLK - 1) / SCAN_BLK)   // 98

// ---------------- scratch (device globals; no allocation allowed) ----------
__device__ __half g_h[(size_t)N_NODES * D];    // 25.6 MB: h = x @ W^T (fp16)
__device__ int    g_deg[N_NODES];              // per-row degree
__device__ int    g_off[N_NODES];              // exclusive prefix (row start)
__device__ int    g_cur[N_NODES];              // fill cursor
__device__ int    g_bsum[NSCAN_BLKS];          // scan block sums
__device__ int2   g_epair[N_EDGES];            // {col, val-as-bits} grouped by row

__device__ __forceinline__ unsigned f2h2(float lo, float hi) {
    __half2 h = __floats2half2_rn(lo, hi);
    return *reinterpret_cast<unsigned*>(&h);
}

// ---------------------------------------------------------------------------
// Tensor-core GEMM: h[n][o] = sum_k x[n][k] * W[o][k]
// mma.sync.m16n8k16 row.col, fp16 inputs (converted in registers), fp32 accum.
// W [o][k] row-major IS B col-major for row.col mma -> no transpose needed.
// Block: 256 thr = 8 warps (4 along M x 2 along N). Block tile 128x128, K=128.
// Warp tile: 32(M) x 64(N) = 2 m-tiles x 8 n-tiles.
// ---------------------------------------------------------------------------
__global__ __launch_bounds__(256) void gemm_tc_kernel(const float* __restrict__ x,
                                                      const float* __restrict__ W) {
    const int wid    = threadIdx.x >> 5;
    const int lane   = threadIdx.x & 31;
    const int warp_m = wid & 3;
    const int warp_n = wid >> 2;
    const int m_warp = blockIdx.x * 128 + warp_m * 32;
    const int n_warp = warp_n * 64;
    const int g  = lane >> 2;        // 0..7
    const int tc = (lane & 3) << 1;  // 0,2,4,6

    float acc[2][8][4];
#pragma unroll
    for (int mt = 0; mt < 2; mt++)
#pragma unroll
        for (int nt = 0; nt < 8; nt++)
#pragma unroll
            for (int i = 0; i < 4; i++) acc[mt][nt][i] = 0.f;

    // Row base pointers, clamped (rows >= N_NODES read row N_NODES-1; discarded at store)
    const float* xr[2][2];
#pragma unroll
    for (int mt = 0; mt < 2; mt++) {
        int r0 = m_warp + mt * 16 + g;
        int r1 = r0 + 8;
        if (r0 >= N_NODES) r0 = N_NODES - 1;
        if (r1 >= N_NODES) r1 = N_NODES - 1;
        xr[mt][0] = &x[(size_t)r0 * D];
        xr[mt][1] = &x[(size_t)r1 * D];
    }

#pragma unroll
    for (int ks = 0; ks < 8; ks++) {
        const int k0 = ks * 16 + tc;

        // A fragments (per PTX m16n8k16 .f16 layout):
        // reg0:(m=g,k=tc) reg1:(m=g+8,k=tc) reg2:(m=g,k=tc+8) reg3:(m=g+8,k=tc+8)
        unsigned a[2][4];
#pragma unroll
        for (int mt = 0; mt < 2; mt++) {
            float2 v0 = *(const float2*)(xr[mt][0] + k0);
            float2 v1 = *(const float2*)(xr[mt][1] + k0);
            float2 v2 = *(const float2*)(xr[mt][0] + k0 + 8);
            float2 v3 = *(const float2*)(xr[mt][1] + k0 + 8);
            a[mt][0] = f2h2(v0.x, v0.y);
            a[mt][1] = f2h2(v1.x, v1.y);
            a[mt][2] = f2h2(v2.x, v2.y);
            a[mt][3] = f2h2(v3.x, v3.y);
        }

        // B fragments: b0:(k=tc..tc+1, n=g) b1:(k=tc+8..tc+9, n=g)
#pragma unroll
        for (int nt = 0; nt < 8; nt++) {
            const int o = n_warp + nt * 8 + g;
            const float* q = &W[(size_t)o * D + k0];
            float2 w0 = *(const float2*)q;
            float2 w1 = *(const float2*)(q + 8);
            unsigned b0 = f2h2(w0.x, w0.y);
            unsigned b1 = f2h2(w1.x, w1.y);
#pragma unroll
            for (int mt = 0; mt < 2; mt++) {
                asm volatile(
                    "mma.sync.aligned.m16n8k16.row.col.f32.f16.f16.f32 "
                    "{%0,%1,%2,%3}, {%4,%5,%6,%7}, {%8,%9}, {%0,%1,%2,%3};\n"
                    : "+f"(acc[mt][nt][0]), "+f"(acc[mt][nt][1]),
                      "+f"(acc[mt][nt][2]), "+f"(acc[mt][nt][3])
                    : "r"(a[mt][0]), "r"(a[mt][1]), "r"(a[mt][2]), "r"(a[mt][3]),
                      "r"(b0), "r"(b1));
            }
        }
    }

    // Store h as fp16. D frag: d0,d1:(m=g, n=tc..tc+1)  d2,d3:(m=g+8, same)
#pragma unroll
    for (int mt = 0; mt < 2; mt++) {
        int r0 = m_warp + mt * 16 + g;
#pragma unroll
        for (int nt = 0; nt < 8; nt++) {
            int col = n_warp + nt * 8 + tc;
            if (r0 < N_NODES) {
                unsigned p = f2h2(acc[mt][nt][0], acc[mt][nt][1]);
                *(unsigned*)&g_h[(size_t)r0 * D + col] = p;
            }
            if (r0 + 8 < N_NODES) {
                unsigned p = f2h2(acc[mt][nt][2], acc[mt][nt][3]);
                *(unsigned*)&g_h[(size_t)(r0 + 8) * D + col] = p;
            }
        }
    }
}

// ---------------------------------------------------------------------------
// CSR build
// ---------------------------------------------------------------------------
__global__ void zero_deg_kernel() {
    int i = blockIdx.x * blockDim.x + threadIdx.x;
    if (i < N_NODES) g_deg[i] = 0;
}

__global__ void count_kernel(const int4* __restrict__ rows4) {
    int t = blockIdx.x * blockDim.x + threadIdx.x;
    if (t < N_EDGES / 4) {
        int4 r = rows4[t];
        atomicAdd(&g_deg[r.x], 1);
        atomicAdd(&g_deg[r.y], 1);
        atomicAdd(&g_deg[r.z], 1);
        atomicAdd(&g_deg[r.w], 1);
    }
}

__global__ __launch_bounds__(SCAN_BLK) void scan1_kernel() {
    __shared__ int s[SCAN_BLK];
    int i = blockIdx.x * SCAN_BLK + threadIdx.x;
    int v = (i < N_NODES) ? g_deg[i] : 0;
    s[threadIdx.x] = v;
    __syncthreads();
#pragma unroll
    for (int d = 1; d < SCAN_BLK; d <<= 1) {
        int t = 0;
        if (threadIdx.x >= d) t = s[threadIdx.x - d];
        __syncthreads();
        if (threadIdx.x >= d) s[threadIdx.x] += t;
        __syncthreads();
    }
    if (i < N_NODES) g_off[i] = s[threadIdx.x] - v;
    if (threadIdx.x == SCAN_BLK - 1) g_bsum[blockIdx.x] = s[SCAN_BLK - 1];
}

// Parallel exclusive scan of the 98 block sums (128-thread Hillis-Steele)
__global__ __launch_bounds__(128) void scan2_kernel() {
    __shared__ int s[128];
    int i = threadIdx.x;
    int v = (i < NSCAN_BLKS) ? g_bsum[i] : 0;
    s[i] = v;
    __syncthreads();
#pragma unroll
    for (int d = 1; d < 128; d <<= 1) {
        int t = (i >= d) ? s[i - d] : 0;
        __syncthreads();
        s[i] += t;
        __syncthreads();
    }
    if (i < NSCAN_BLKS) g_bsum[i] = s[i] - v;   // exclusive
}

__global__ void scan3_kernel() {
    int i = blockIdx.x * blockDim.x + threadIdx.x;
    if (i < N_NODES) {
        int o = g_off[i] + g_bsum[i / SCAN_BLK];
        g_off[i] = o;
        g_cur[i] = o;
    }
}

__global__ void fill_kernel(const int4* __restrict__ rows4,
                            const int4* __restrict__ cols4,
                            const float4* __restrict__ vals4) {
    int t = blockIdx.x * blockDim.x + threadIdx.x;
    if (t < N_EDGES / 4) {
        int4   r = rows4[t];
        int4   c = cols4[t];
        float4 v = vals4[t];
        int p0 = atomicAdd(&g_cur[r.x], 1);
        g_epair[p0] = make_int2(c.x, __float_as_int(v.x));
        int p1 = atomicAdd(&g_cur[r.y], 1);
        g_epair[p1] = make_int2(c.y, __float_as_int(v.y));
        int p2 = atomicAdd(&g_cur[r.z], 1);
        g_epair[p2] = make_int2(c.z, __float_as_int(v.z));
        int p3 = atomicAdd(&g_cur[r.w], 1);
        g_epair[p3] = make_int2(c.w, __float_as_int(v.w));
    }
}

// ---------------------------------------------------------------------------
// Aggregate + ReLU: one warp per node; lane handles 4 features (8B fp16 load)
// ---------------------------------------------------------------------------
__device__ __forceinline__ void fma_h4(float4& acc, float v, uint2 raw) {
    float2 lo = __half22float2(*(half2*)&raw.x);
    float2 hi = __half22float2(*(half2*)&raw.y);
    acc.x += v * lo.x;
    acc.y += v * lo.y;
    acc.z += v * hi.x;
    acc.w += v * hi.y;
}

__global__ __launch_bounds__(256) void aggregate_kernel(float* __restrict__ out) {
    int n = blockIdx.x * 8 + (threadIdx.x >> 5);
    if (n >= N_NODES) return;
    int lane = threadIdx.x & 31;

    int s = g_off[n];
    int d = g_deg[n];
    int fofs = lane * 4;

    float4 acc = make_float4(0.f, 0.f, 0.f, 0.f);

    int j = 0;
    for (; j + 4 <= d; j += 4) {
        int2 p0 = g_epair[s + j + 0];
        int2 p1 = g_epair[s + j + 1];
        int2 p2 = g_epair[s + j + 2];
        int2 p3 = g_epair[s + j + 3];
        uint2 h0 = *(const uint2*)&g_h[(size_t)p0.x * D + fofs];
        uint2 h1 = *(const uint2*)&g_h[(size_t)p1.x * D + fofs];
        uint2 h2 = *(const uint2*)&g_h[(size_t)p2.x * D + fofs];
        uint2 h3 = *(const uint2*)&g_h[(size_t)p3.x * D + fofs];
        fma_h4(acc, __int_as_float(p0.y), h0);
        fma_h4(acc, __int_as_float(p1.y), h1);
        fma_h4(acc, __int_as_float(p2.y), h2);
        fma_h4(acc, __int_as_float(p3.y), h3);
    }
    for (; j < d; j++) {
        int2 p = g_epair[s + j];
        uint2 hv = *(const uint2*)&g_h[(size_t)p.x * D + fofs];
        fma_h4(acc, __int_as_float(p.y), hv);
    }

    acc.x = fmaxf(acc.x, 0.f);
    acc.y = fmaxf(acc.y, 0.f);
    acc.z = fmaxf(acc.z, 0.f);
    acc.w = fmaxf(acc.w, 0.f);
    *(float4*)&out[(size_t)n * D + fofs] = acc;
}

// ---------------------------------------------------------------------------
// kernel_launch
// ---------------------------------------------------------------------------
extern "C" void kernel_launch(void* const* d_in, const int* in_sizes, int n_in,
                              void* d_out, int out_size) {
    const float* x    = (const float*)d_in[0];
    const int*   rows = (const int*)d_in[1];
    const int*   cols = (const int*)d_in[2];
    const float* vals = (const float*)d_in[3];
    const float* W    = (const float*)d_in[4];
    float*       out  = (float*)d_out;

    const int EB4 = (N_EDGES / 4 + 255) / 256;  // 3125
    const int NB  = (N_NODES + 255) / 256;      // 391

    // Dense path: tensor-core GEMM straight from fp32 inputs
    gemm_tc_kernel<<<(N_NODES + 127) / 128, 256>>>(x, W);

    // CSR build
    zero_deg_kernel<<<NB, 256>>>();
    count_kernel<<<EB4, 256>>>((const int4*)rows);
    scan1_kernel<<<NSCAN_BLKS, SCAN_BLK>>>();
    scan2_kernel<<<1, 128>>>();
    scan3_kernel<<<NB, 256>>>();
    fill_kernel<<<EB4, 256>>>((const int4*)rows, (const int4*)cols,
                              (const float4*)vals);

    // Gather-accumulate + fused ReLU
    aggregate_kernel<<<(N_NODES + 7) / 8, 256>>>(out);
}

// round 6
// speedup vs baseline: 5.1745x; 1.0305x over previous
#include <cuda_runtime.h>
#include <cuda_fp16.h>

#define N_NODES 100000
#define N_EDGES 3200000
#define D 128

#define SCAN_BLK 1024
#define NSCAN_BLKS ((N_NODES + SCAN_BLK - 1) / SCAN_BLK)   // 98

// ---------------- scratch (device globals; no allocation allowed) ----------
__device__ __half g_h[(size_t)N_NODES * D];    // 25.6 MB: h = x @ W^T (fp16)
__device__ __half g_Wh[D * D];                 // W in fp16, [o][k] row-major
__device__ int    g_deg[N_NODES];              // per-row degree
__device__ int    g_off[N_NODES];              // exclusive prefix (row start)
__device__ int    g_cur[N_NODES];              // fill cursor
__device__ int    g_bsum[NSCAN_BLKS];          // scan block sums
__device__ int2   g_epair[N_EDGES];            // {col, val-as-bits} grouped by row

__device__ __forceinline__ unsigned f2h2(float lo, float hi) {
    __half2 h = __floats2half2_rn(lo, hi);
    return *reinterpret_cast<unsigned*>(&h);
}

// ---------------------------------------------------------------------------
// W fp32 -> fp16 (once; 16K elems)
// ---------------------------------------------------------------------------
__global__ void convert_w_kernel(const float* __restrict__ W) {
    int i = blockIdx.x * blockDim.x + threadIdx.x;
    if (i < D * D / 2) {
        float2 v = ((const float2*)W)[i];
        ((__half2*)g_Wh)[i] = __floats2half2_rn(v.x, v.y);
    }
}

// ---------------------------------------------------------------------------
// Tensor-core GEMM: h[n][o] = sum_k x[n][k] * W[o][k]
// mma.sync.m16n8k16 row.col, fp32 accum. A converted in regs; B read as fp16.
// Block: 128 thr = 4 warps along M. Warp tile: 32(M) x 128(N) -> x loaded ONCE.
// ---------------------------------------------------------------------------
__global__ __launch_bounds__(128) void gemm_tc_kernel(const float* __restrict__ x) {
    const int wid  = threadIdx.x >> 5;
    const int lane = threadIdx.x & 31;
    const int m_warp = blockIdx.x * 128 + wid * 32;
    const int g  = lane >> 2;        // 0..7
    const int tc = (lane & 3) << 1;  // 0,2,4,6

    float acc[2][16][4];
#pragma unroll
    for (int mt = 0; mt < 2; mt++)
#pragma unroll
        for (int nt = 0; nt < 16; nt++)
#pragma unroll
            for (int i = 0; i < 4; i++) acc[mt][nt][i] = 0.f;

    // Row base pointers, clamped (rows >= N_NODES read row N_NODES-1; dropped at store)
    const float* xr[2][2];
#pragma unroll
    for (int mt = 0; mt < 2; mt++) {
        int r0 = m_warp + mt * 16 + g;
        int r1 = r0 + 8;
        if (r0 >= N_NODES) r0 = N_NODES - 1;
        if (r1 >= N_NODES) r1 = N_NODES - 1;
        xr[mt][0] = &x[(size_t)r0 * D];
        xr[mt][1] = &x[(size_t)r1 * D];
    }

#pragma unroll
    for (int ks = 0; ks < 8; ks++) {
        const int k0 = ks * 16 + tc;

        // A fragments (m16n8k16 .f16 layout):
        // a0:(m=g,k=tc) a1:(m=g+8,k=tc) a2:(m=g,k=tc+8) a3:(m=g+8,k=tc+8)
        unsigned a[2][4];
#pragma unroll
        for (int mt = 0; mt < 2; mt++) {
            float2 v0 = *(const float2*)(xr[mt][0] + k0);
            float2 v1 = *(const float2*)(xr[mt][1] + k0);
            float2 v2 = *(const float2*)(xr[mt][0] + k0 + 8);
            float2 v3 = *(const float2*)(xr[mt][1] + k0 + 8);
            a[mt][0] = f2h2(v0.x, v0.y);
            a[mt][1] = f2h2(v1.x, v1.y);
            a[mt][2] = f2h2(v2.x, v2.y);
            a[mt][3] = f2h2(v3.x, v3.y);
        }

        // B fragments from preconverted fp16 W (L1-resident):
        // b0:(k=tc..tc+1, n=g)  b1:(k=tc+8..tc+9, n=g)
#pragma unroll
        for (int nt = 0; nt < 16; nt++) {
            const int o = nt * 8 + g;
            const __half* q = &g_Wh[(size_t)o * D + k0];
            unsigned b0 = *(const unsigned*)q;
            unsigned b1 = *(const unsigned*)(q + 8);
#pragma unroll
            for (int mt = 0; mt < 2; mt++) {
                asm volatile(
                    "mma.sync.aligned.m16n8k16.row.col.f32.f16.f16.f32 "
                    "{%0,%1,%2,%3}, {%4,%5,%6,%7}, {%8,%9}, {%0,%1,%2,%3};\n"
                    : "+f"(acc[mt][nt][0]), "+f"(acc[mt][nt][1]),
                      "+f"(acc[mt][nt][2]), "+f"(acc[mt][nt][3])
                    : "r"(a[mt][0]), "r"(a[mt][1]), "r"(a[mt][2]), "r"(a[mt][3]),
                      "r"(b0), "r"(b1));
            }
        }
    }

    // Store h as fp16. D frag: d0,d1:(m=g, n=tc..tc+1)  d2,d3:(m=g+8, same)
#pragma unroll
    for (int mt = 0; mt < 2; mt++) {
        int r0 = m_warp + mt * 16 + g;
#pragma unroll
        for (int nt = 0; nt < 16; nt++) {
            int col = nt * 8 + tc;
            if (r0 < N_NODES) {
                unsigned p = f2h2(acc[mt][nt][0], acc[mt][nt][1]);
                *(unsigned*)&g_h[(size_t)r0 * D + col] = p;
            }
            if (r0 + 8 < N_NODES) {
                unsigned p = f2h2(acc[mt][nt][2], acc[mt][nt][3]);
                *(unsigned*)&g_h[(size_t)(r0 + 8) * D + col] = p;
            }
        }
    }
}

// ---------------------------------------------------------------------------
// CSR build
// ---------------------------------------------------------------------------
__global__ void zero_deg_kernel() {
    int i = blockIdx.x * blockDim.x + threadIdx.x;
    if (i < N_NODES) g_deg[i] = 0;
}

__global__ void count_kernel(const int4* __restrict__ rows4) {
    int t = blockIdx.x * blockDim.x + threadIdx.x;
    if (t < N_EDGES / 4) {
        int4 r = rows4[t];
        atomicAdd(&g_deg[r.x], 1);
        atomicAdd(&g_deg[r.y], 1);
        atomicAdd(&g_deg[r.z], 1);
        atomicAdd(&g_deg[r.w], 1);
    }
}

__global__ __launch_bounds__(SCAN_BLK) void scan1_kernel() {
    __shared__ int s[SCAN_BLK];
    int i = blockIdx.x * SCAN_BLK + threadIdx.x;
    int v = (i < N_NODES) ? g_deg[i] : 0;
    s[threadIdx.x] = v;
    __syncthreads();
#pragma unroll
    for (int d = 1; d < SCAN_BLK; d <<= 1) {
        int t = 0;
        if (threadIdx.x >= d) t = s[threadIdx.x - d];
        __syncthreads();
        if (threadIdx.x >= d) s[threadIdx.x] += t;
        __syncthreads();
    }
    if (i < N_NODES) g_off[i] = s[threadIdx.x] - v;
    if (threadIdx.x == SCAN_BLK - 1) g_bsum[blockIdx.x] = s[SCAN_BLK - 1];
}

// Parallel exclusive scan of the 98 block sums
__global__ __launch_bounds__(128) void scan2_kernel() {
    __shared__ int s[128];
    int i = threadIdx.x;
    int v = (i < NSCAN_BLKS) ? g_bsum[i] : 0;
    s[i] = v;
    __syncthreads();
#pragma unroll
    for (int d = 1; d < 128; d <<= 1) {
        int t = (i >= d) ? s[i - d] : 0;
        __syncthreads();
        s[i] += t;
        __syncthreads();
    }
    if (i < NSCAN_BLKS) g_bsum[i] = s[i] - v;   // exclusive
}

__global__ void scan3_kernel() {
    int i = blockIdx.x * blockDim.x + threadIdx.x;
    if (i < N_NODES) {
        int o = g_off[i] + g_bsum[i / SCAN_BLK];
        g_off[i] = o;
        g_cur[i] = o;
    }
}

__global__ void fill_kernel(const int4* __restrict__ rows4,
                            const int4* __restrict__ cols4,
                            const float4* __restrict__ vals4) {
    int t = blockIdx.x * blockDim.x + threadIdx.x;
    if (t < N_EDGES / 4) {
        int4   r = rows4[t];
        int4   c = cols4[t];
        float4 v = vals4[t];
        int p0 = atomicAdd(&g_cur[r.x], 1);
        g_epair[p0] = make_int2(c.x, __float_as_int(v.x));
        int p1 = atomicAdd(&g_cur[r.y], 1);
        g_epair[p1] = make_int2(c.y, __float_as_int(v.y));
        int p2 = atomicAdd(&g_cur[r.z], 1);
        g_epair[p2] = make_int2(c.z, __float_as_int(v.z));
        int p3 = atomicAdd(&g_cur[r.w], 1);
        g_epair[p3] = make_int2(c.w, __float_as_int(v.w));
    }
}

// ---------------------------------------------------------------------------
// Aggregate + ReLU: one warp per node; lane handles 4 features (8B fp16 load)
// ---------------------------------------------------------------------------
__device__ __forceinline__ void fma_h4(float4& acc, float v, uint2 raw) {
    float2 lo = __half22float2(*(half2*)&raw.x);
    float2 hi = __half22float2(*(half2*)&raw.y);
    acc.x += v * lo.x;
    acc.y += v * lo.y;
    acc.z += v * hi.x;
    acc.w += v * hi.y;
}

__global__ __launch_bounds__(256) void aggregate_kernel(float* __restrict__ out) {
    int n = blockIdx.x * 8 + (threadIdx.x >> 5);
    if (n >= N_NODES) return;
    int lane = threadIdx.x & 31;

    int s = g_off[n];
    int d = g_deg[n];
    int fofs = lane * 4;

    float4 acc = make_float4(0.f, 0.f, 0.f, 0.f);

    int j = 0;
    for (; j + 4 <= d; j += 4) {
        int2 p0 = g_epair[s + j + 0];
        int2 p1 = g_epair[s + j + 1];
        int2 p2 = g_epair[s + j + 2];
        int2 p3 = g_epair[s + j + 3];
        uint2 h0 = *(const uint2*)&g_h[(size_t)p0.x * D + fofs];
        uint2 h1 = *(const uint2*)&g_h[(size_t)p1.x * D + fofs];
        uint2 h2 = *(const uint2*)&g_h[(size_t)p2.x * D + fofs];
        uint2 h3 = *(const uint2*)&g_h[(size_t)p3.x * D + fofs];
        fma_h4(acc, __int_as_float(p0.y), h0);
        fma_h4(acc, __int_as_float(p1.y), h1);
        fma_h4(acc, __int_as_float(p2.y), h2);
        fma_h4(acc, __int_as_float(p3.y), h3);
    }
    for (; j < d; j++) {
        int2 p = g_epair[s + j];
        uint2 hv = *(const uint2*)&g_h[(size_t)p.x * D + fofs];
        fma_h4(acc, __int_as_float(p.y), hv);
    }

    acc.x = fmaxf(acc.x, 0.f);
    acc.y = fmaxf(acc.y, 0.f);
    acc.z = fmaxf(acc.z, 0.f);
    acc.w = fmaxf(acc.w, 0.f);
    *(float4*)&out[(size_t)n * D + fofs] = acc;
}

// ---------------------------------------------------------------------------
// kernel_launch
// ---------------------------------------------------------------------------
extern "C" void kernel_launch(void* const* d_in, const int* in_sizes, int n_in,
                              void* d_out, int out_size) {
    const float* x    = (const float*)d_in[0];
    const int*   rows = (const int*)d_in[1];
    const int*   cols = (const int*)d_in[2];
    const float* vals = (const float*)d_in[3];
    const float* W    = (const float*)d_in[4];
    float*       out  = (float*)d_out;

    const int EB4 = (N_EDGES / 4 + 255) / 256;  // 3125
    const int NB  = (N_NODES + 255) / 256;      // 391

    // Dense path
    convert_w_kernel<<<(D * D / 2 + 255) / 256, 256>>>(W);
    gemm_tc_kernel<<<(N_NODES + 127) / 128, 128>>>(x);

    // CSR build
    zero_deg_kernel<<<NB, 256>>>();
    count_kernel<<<EB4, 256>>>((const int4*)rows);
    scan1_kernel<<<NSCAN_BLKS, SCAN_BLK>>>();
    scan2_kernel<<<1, 128>>>();
    scan3_kernel<<<NB, 256>>>();
    fill_kernel<<<EB4, 256>>>((const int4*)rows, (const int4*)cols,
                              (const float4*)vals);

    // Gather-accumulate + fused ReLU
    aggregate_kernel<<<(N_NODES + 7) / 8, 256>>>(out);
}

// round 9
// speedup vs baseline: 5.2803x; 1.0204x over previous
#include <cuda_runtime.h>
#include <cuda_fp16.h>

#define N_NODES 100000
#define N_EDGES 3200000
#define D 128

#define SCAN_BLK 1024
#define NSCAN_BLKS ((N_NODES + SCAN_BLK - 1) / SCAN_BLK)   // 98

// ---------------- scratch (device globals; no allocation allowed) ----------
__device__ __half g_h[(size_t)N_NODES * D];    // 25.6 MB: h = x @ W^T (fp16)
__device__ __half g_Wh[D * D];                 // W in fp16, [o][k] row-major
__device__ int    g_deg[N_NODES];              // per-row degree
__device__ int    g_off[N_NODES];              // exclusive prefix (row start)
__device__ int    g_cur[N_NODES];              // fill cursor
__device__ int    g_bsum[NSCAN_BLKS];          // scan block sums
__device__ int2   g_epair[N_EDGES];            // {col, val-as-bits} grouped by row

__device__ __forceinline__ unsigned f2h2(float lo, float hi) {
    __half2 h = __floats2half2_rn(lo, hi);
    return *reinterpret_cast<unsigned*>(&h);
}

// ---------------------------------------------------------------------------
// W fp32 -> fp16 (once; 16K elems)
// ---------------------------------------------------------------------------
__global__ void convert_w_kernel(const float* __restrict__ W) {
    int i = blockIdx.x * blockDim.x + threadIdx.x;
    if (i < D * D / 2) {
        float2 v = ((const float2*)W)[i];
        ((__half2*)g_Wh)[i] = __floats2half2_rn(v.x, v.y);
    }
}

// ---------------------------------------------------------------------------
// Tensor-core GEMM: h[n][o] = sum_k x[n][k] * W[o][k]
// mma.sync.m16n8k16 row.col, fp32 accum. A converted in regs; B read as fp16.
// Block: 128 thr = 4 warps along M. Warp tile: 32(M) x 128(N) -> x loaded ONCE.
// ---------------------------------------------------------------------------
__global__ __launch_bounds__(128) void gemm_tc_kernel(const float* __restrict__ x) {
    const int wid  = threadIdx.x >> 5;
    const int lane = threadIdx.x & 31;
    const int m_warp = blockIdx.x * 128 + wid * 32;
    const int g  = lane >> 2;        // 0..7
    const int tc = (lane & 3) << 1;  // 0,2,4,6

    float acc[2][16][4];
#pragma unroll
    for (int mt = 0; mt < 2; mt++)
#pragma unroll
        for (int nt = 0; nt < 16; nt++)
#pragma unroll
            for (int i = 0; i < 4; i++) acc[mt][nt][i] = 0.f;

    const float* xr[2][2];
#pragma unroll
    for (int mt = 0; mt < 2; mt++) {
        int r0 = m_warp + mt * 16 + g;
        int r1 = r0 + 8;
        if (r0 >= N_NODES) r0 = N_NODES - 1;
        if (r1 >= N_NODES) r1 = N_NODES - 1;
        xr[mt][0] = &x[(size_t)r0 * D];
        xr[mt][1] = &x[(size_t)r1 * D];
    }

#pragma unroll
    for (int ks = 0; ks < 8; ks++) {
        const int k0 = ks * 16 + tc;

        unsigned a[2][4];
#pragma unroll
        for (int mt = 0; mt < 2; mt++) {
            float2 v0 = *(const float2*)(xr[mt][0] + k0);
            float2 v1 = *(const float2*)(xr[mt][1] + k0);
            float2 v2 = *(const float2*)(xr[mt][0] + k0 + 8);
            float2 v3 = *(const float2*)(xr[mt][1] + k0 + 8);
            a[mt][0] = f2h2(v0.x, v0.y);
            a[mt][1] = f2h2(v1.x, v1.y);
            a[mt][2] = f2h2(v2.x, v2.y);
            a[mt][3] = f2h2(v3.x, v3.y);
        }

#pragma unroll
        for (int nt = 0; nt < 16; nt++) {
            const int o = nt * 8 + g;
            const __half* q = &g_Wh[(size_t)o * D + k0];
            unsigned b0 = *(const unsigned*)q;
            unsigned b1 = *(const unsigned*)(q + 8);
#pragma unroll
            for (int mt = 0; mt < 2; mt++) {
                asm volatile(
                    "mma.sync.aligned.m16n8k16.row.col.f32.f16.f16.f32 "
                    "{%0,%1,%2,%3}, {%4,%5,%6,%7}, {%8,%9}, {%0,%1,%2,%3};\n"
                    : "+f"(acc[mt][nt][0]), "+f"(acc[mt][nt][1]),
                      "+f"(acc[mt][nt][2]), "+f"(acc[mt][nt][3])
                    : "r"(a[mt][0]), "r"(a[mt][1]), "r"(a[mt][2]), "r"(a[mt][3]),
                      "r"(b0), "r"(b1));
            }
        }
    }

#pragma unroll
    for (int mt = 0; mt < 2; mt++) {
        int r0 = m_warp + mt * 16 + g;
#pragma unroll
        for (int nt = 0; nt < 16; nt++) {
            int col = nt * 8 + tc;
            if (r0 < N_NODES) {
                unsigned p = f2h2(acc[mt][nt][0], acc[mt][nt][1]);
                *(unsigned*)&g_h[(size_t)r0 * D + col] = p;
            }
            if (r0 + 8 < N_NODES) {
                unsigned p = f2h2(acc[mt][nt][2], acc[mt][nt][3]);
                *(unsigned*)&g_h[(size_t)(r0 + 8) * D + col] = p;
            }
        }
    }
}

// ---------------------------------------------------------------------------
// CSR build
// ---------------------------------------------------------------------------
__global__ void zero_deg_kernel() {
    int i = blockIdx.x * blockDim.x + threadIdx.x;
    if (i < N_NODES) g_deg[i] = 0;
}

__global__ void count_kernel(const int4* __restrict__ rows4) {
    int t = blockIdx.x * blockDim.x + threadIdx.x;
    if (t < N_EDGES / 4) {
        int4 r = rows4[t];
        atomicAdd(&g_deg[r.x], 1);
        atomicAdd(&g_deg[r.y], 1);
        atomicAdd(&g_deg[r.z], 1);
        atomicAdd(&g_deg[r.w], 1);
    }
}

__global__ __launch_bounds__(SCAN_BLK) void scan1_kernel() {
    __shared__ int s[SCAN_BLK];
    int i = blockIdx.x * SCAN_BLK + threadIdx.x;
    int v = (i < N_NODES) ? g_deg[i] : 0;
    s[threadIdx.x] = v;
    __syncthreads();
#pragma unroll
    for (int d = 1; d < SCAN_BLK; d <<= 1) {
        int t = 0;
        if (threadIdx.x >= d) t = s[threadIdx.x - d];
        __syncthreads();
        if (threadIdx.x >= d) s[threadIdx.x] += t;
        __syncthreads();
    }
    if (i < N_NODES) g_off[i] = s[threadIdx.x] - v;
    if (threadIdx.x == SCAN_BLK - 1) g_bsum[blockIdx.x] = s[SCAN_BLK - 1];
}

__global__ __launch_bounds__(128) void scan2_kernel() {
    __shared__ int s[128];
    int i = threadIdx.x;
    int v = (i < NSCAN_BLKS) ? g_bsum[i] : 0;
    s[i] = v;
    __syncthreads();
#pragma unroll
    for (int d = 1; d < 128; d <<= 1) {
        int t = (i >= d) ? s[i - d] : 0;
        __syncthreads();
        s[i] += t;
        __syncthreads();
    }
    if (i < NSCAN_BLKS) g_bsum[i] = s[i] - v;   // exclusive
}

__global__ void scan3_kernel() {
    int i = blockIdx.x * blockDim.x + threadIdx.x;
    if (i < N_NODES) {
        int o = g_off[i] + g_bsum[i / SCAN_BLK];
        g_off[i] = o;
        g_cur[i] = o;
    }
}

__global__ void fill_kernel(const int4* __restrict__ rows4,
                            const int4* __restrict__ cols4,
                            const float4* __restrict__ vals4) {
    int t = blockIdx.x * blockDim.x + threadIdx.x;
    if (t < N_EDGES / 4) {
        int4   r = rows4[t];
        int4   c = cols4[t];
        float4 v = vals4[t];
        int p0 = atomicAdd(&g_cur[r.x], 1);
        g_epair[p0] = make_int2(c.x, __float_as_int(v.x));
        int p1 = atomicAdd(&g_cur[r.y], 1);
        g_epair[p1] = make_int2(c.y, __float_as_int(v.y));
        int p2 = atomicAdd(&g_cur[r.z], 1);
        g_epair[p2] = make_int2(c.z, __float_as_int(v.z));
        int p3 = atomicAdd(&g_cur[r.w], 1);
        g_epair[p3] = make_int2(c.w, __float_as_int(v.w));
    }
}

// ---------------------------------------------------------------------------
// Aggregate + ReLU: one warp per node; lane handles 4 features (8B fp16 load)
// ---------------------------------------------------------------------------
__device__ __forceinline__ void fma_h4(float4& acc, float v, uint2 raw) {
    float2 lo = __half22float2(*(half2*)&raw.x);
    float2 hi = __half22float2(*(half2*)&raw.y);
    acc.x += v * lo.x;
    acc.y += v * lo.y;
    acc.z += v * hi.x;
    acc.w += v * hi.y;
}

__global__ __launch_bounds__(256) void aggregate_kernel(float* __restrict__ out) {
    int n = blockIdx.x * 8 + (threadIdx.x >> 5);
    if (n >= N_NODES) return;
    int lane = threadIdx.x & 31;

    int s = g_off[n];
    int d = g_deg[n];
    int fofs = lane * 4;

    float4 acc = make_float4(0.f, 0.f, 0.f, 0.f);

    int j = 0;
    for (; j + 4 <= d; j += 4) {
        int2 p0 = g_epair[s + j + 0];
        int2 p1 = g_epair[s + j + 1];
        int2 p2 = g_epair[s + j + 2];
        int2 p3 = g_epair[s + j + 3];
        uint2 h0 = *(const uint2*)&g_h[(size_t)p0.x * D + fofs];
        uint2 h1 = *(const uint2*)&g_h[(size_t)p1.x * D + fofs];
        uint2 h2 = *(const uint2*)&g_h[(size_t)p2.x * D + fofs];
        uint2 h3 = *(const uint2*)&g_h[(size_t)p3.x * D + fofs];
        fma_h4(acc, __int_as_float(p0.y), h0);
        fma_h4(acc, __int_as_float(p1.y), h1);
        fma_h4(acc, __int_as_float(p2.y), h2);
        fma_h4(acc, __int_as_float(p3.y), h3);
    }
    for (; j < d; j++) {
        int2 p = g_epair[s + j];
        uint2 hv = *(const uint2*)&g_h[(size_t)p.x * D + fofs];
        fma_h4(acc, __int_as_float(p.y), hv);
    }

    acc.x = fmaxf(acc.x, 0.f);
    acc.y = fmaxf(acc.y, 0.f);
    acc.z = fmaxf(acc.z, 0.f);
    acc.w = fmaxf(acc.w, 0.f);
    *(float4*)&out[(size_t)n * D + fofs] = acc;
}

// ---------------------------------------------------------------------------
// kernel_launch: dense branch on stream 0, CSR branch on side stream,
// fork/join via events (graph-capturable parallel branches).
// ---------------------------------------------------------------------------
extern "C" void kernel_launch(void* const* d_in, const int* in_sizes, int n_in,
                              void* d_out, int out_size) {
    const float* x    = (const float*)d_in[0];
    const int*   rows = (const int*)d_in[1];
    const int*   cols = (const int*)d_in[2];
    const float* vals = (const float*)d_in[3];
    const float* W    = (const float*)d_in[4];
    float*       out  = (float*)d_out;

    const int EB4 = (N_EDGES / 4 + 255) / 256;  // 3125
    const int NB  = (N_NODES + 255) / 256;      // 391

    // Lazily created side stream + fork/join events (host objects, not device
    // memory). Work enqueued per call is identical regardless.
    static cudaStream_t s_side = nullptr;
    static cudaEvent_t  s_fork = nullptr, s_join = nullptr;
    if (!s_side) {
        cudaStreamCreateWithFlags(&s_side, cudaStreamNonBlocking);
        cudaEventCreateWithFlags(&s_fork, cudaEventDisableTiming);
        cudaEventCreateWithFlags(&s_join, cudaEventDisableTiming);
    }

    // Fork: side stream branches off the capture-origin stream (0)
    cudaEventRecord(s_fork, 0);
    cudaStreamWaitEvent(s_side, s_fork, 0);

    // Dense branch (stream 0): convert W, GEMM -> g_h
    convert_w_kernel<<<(D * D / 2 + 255) / 256, 256>>>(W);
    gemm_tc_kernel<<<(N_NODES + 127) / 128, 128>>>(x);

    // CSR branch (side stream): zero -> count -> scan -> fill -> g_epair
    zero_deg_kernel<<<NB, 256, 0, s_side>>>();
    count_kernel<<<EB4, 256, 0, s_side>>>((const int4*)rows);
    scan1_kernel<<<NSCAN_BLKS, SCAN_BLK, 0, s_side>>>();
    scan2_kernel<<<1, 128, 0, s_side>>>();
    scan3_kernel<<<NB, 256, 0, s_side>>>();
    fill_kernel<<<EB4, 256, 0, s_side>>>((const int4*)rows, (const int4*)cols,
                                         (const float4*)vals);

    // Join: stream 0 waits for CSR branch
    cudaEventRecord(s_join, s_side);
    cudaStreamWaitEvent(0, s_join, 0);

    // Aggregate + fused ReLU (needs g_h and g_epair)
    aggregate_kernel<<<(N_NODES + 7) / 8, 256>>>(out);
}